// round 16
// baseline (speedup 1.0000x reference)
#include <cuda_runtime.h>
#include <cstdint>
#include <cstddef>

#define N_NODE 50000
#define N_EDGE 625000
#define FD 128
#define EPS 1e-5f
#define TM 128

__device__ float g_agg[(size_t)N_NODE * FD];
__device__ float g_Wt1[128 * 256];
__device__ float g_Wt2[128 * 128];
__device__ float g_Wt3[128 * 128];

__device__ __forceinline__ float to_tf32(float x) {
    uint32_t r;
    asm("cvt.rna.tf32.f32 %0, %1;" : "=r"(r) : "f"(x));
    return __uint_as_float(r);
}
__device__ __forceinline__ uint32_t smem_u32(const void* p) {
    uint32_t a;
    asm("{ .reg .u64 t; cvta.to.shared.u64 t, %1; cvt.u32.u64 %0, t; }"
        : "=r"(a) : "l"(p));
    return a;
}
__device__ __forceinline__ void ldsm4(uint32_t a[4], uint32_t addr) {
    asm volatile("ldmatrix.sync.aligned.m8n8.x4.shared.b16 {%0,%1,%2,%3}, [%4];"
                 : "=r"(a[0]), "=r"(a[1]), "=r"(a[2]), "=r"(a[3]) : "r"(addr));
}

#define LOF(x) __uint_as_float((uint32_t)(x))
#define HIF(x) __uint_as_float((uint32_t)((x) >> 32))

#define MMA_TF32(c, a0, a1, a2, a3, b0, b1)                                       \
    asm volatile("mma.sync.aligned.m16n8k8.row.col.f32.tf32.tf32.f32 "            \
                 "{%0,%1,%2,%3}, {%4,%5,%6,%7}, {%8,%9}, {%0,%1,%2,%3};"          \
                 : "+f"((c)[0]), "+f"((c)[1]), "+f"((c)[2]), "+f"((c)[3])         \
                 : "r"(a0), "r"(a1), "r"(a2), "r"(a3), "r"(b0), "r"(b1))

#define CP_ASYNC16(saddr, gptr)                                                   \
    asm volatile("cp.async.cg.shared.global [%0], [%1], 16;"                      \
                 :: "r"(saddr), "l"(gptr) : "memory")
#define CP_COMMIT() asm volatile("cp.async.commit_group;" ::: "memory")
#define CP_WAIT(n)  asm volatile("cp.async.wait_group %0;" :: "n"(n) : "memory")

#define RED4(dst, x, y, z, w)                                                     \
    asm volatile("red.global.add.v4.f32 [%0], {%1,%2,%3,%4};"                     \
                 :: "l"(dst), "f"(x), "f"(y), "f"(z), "f"(w) : "memory")

// ---------------------------------------------------------------------------
// Scatter-add: 4 edges/warp via 2 wide evict_first loads (32B/lane; lanes
// 0-15 hold edge e, 16-31 edge e+1). 4 v4-REDs/lane as before (MLP=4-ish
// in flight, fewer LSU ops). edge_feature streams evict-first so g_agg
// stays L2-resident.
// ---------------------------------------------------------------------------
__global__ void scatter_edges_kernel(const int* __restrict__ em,
                                     const float* __restrict__ ef) {
    int e0 = (blockIdx.x * 8 + (threadIdx.x >> 5)) * 4;
    int lane = threadIdx.x & 31;
    int half = lane >> 4;       // which edge of the pair this lane holds
    int li = lane & 15;         // 16 lanes x 32B = 512B = one edge row
    if (e0 + 3 < N_EDGE) {
        int rA = em[N_EDGE + e0 + half];
        int rB = em[N_EDGE + e0 + 2 + half];
        uint64_t a0, a1, a2, a3, b0, b1, b2, b3;
        const float* p0 = ef + (size_t)(e0 + half) * FD + li * 8;
        const float* p1 = ef + (size_t)(e0 + 2 + half) * FD + li * 8;
        asm volatile("ld.global.L2::evict_first.v4.b64 {%0,%1,%2,%3}, [%4];"
                     : "=l"(a0), "=l"(a1), "=l"(a2), "=l"(a3) : "l"(p0));
        asm volatile("ld.global.L2::evict_first.v4.b64 {%0,%1,%2,%3}, [%4];"
                     : "=l"(b0), "=l"(b1), "=l"(b2), "=l"(b3) : "l"(p1));
        float* dA = g_agg + (size_t)rA * FD + li * 8;
        float* dB = g_agg + (size_t)rB * FD + li * 8;
        RED4(dA,     LOF(a0), HIF(a0), LOF(a1), HIF(a1));
        RED4(dA + 4, LOF(a2), HIF(a2), LOF(a3), HIF(a3));
        RED4(dB,     LOF(b0), HIF(b0), LOF(b1), HIF(b1));
        RED4(dB + 4, LOF(b2), HIF(b2), LOF(b3), HIF(b3));
    } else {
        for (int i = 0; i < 4; ++i) {
            int e = e0 + i;
            if (e >= N_EDGE) break;
            int r = em[N_EDGE + e];
            float4 v = *(const float4*)(ef + (size_t)e * FD + lane * 4);
            RED4(g_agg + (size_t)r * FD + lane * 4, v.x, v.y, v.z, v.w);
        }
    }
}

// ---------------------------------------------------------------------------
__global__ void prep_weights_kernel(const float* __restrict__ W1,
                                    const float* __restrict__ W2,
                                    const float* __restrict__ W3) {
    int i = blockIdx.x * blockDim.x + threadIdx.x;
    if (i < 256 * 128) {
        int k = i >> 7, n = i & 127;
        g_Wt1[n * 256 + k] = to_tf32(W1[i]);
    } else if (i < 256 * 128 + 128 * 128) {
        int j = i - 256 * 128;
        int k = j >> 7, n = j & 127;
        g_Wt2[n * 128 + k] = to_tf32(W2[j]);
    } else if (i < 256 * 128 + 2 * 128 * 128) {
        int j = i - 256 * 128 - 128 * 128;
        int k = j >> 7, n = j & 127;
        g_Wt3[n * 128 + k] = to_tf32(W3[j]);
    }
}

// ---------------------------------------------------------------------------
// Fused MLP + LN + residual. Warp tile 32x64 (round-14, frozen).
// ---------------------------------------------------------------------------
#define XS_STRIDE 36
#define WS_STRIDE 36
#define HS_STRIDE 132
#define SMEM_FLOATS (128 * HS_STRIDE + 128 * WS_STRIDE + 128 * XS_STRIDE + 5 * 128 + 512)
#define SMEM_BYTES (SMEM_FLOATS * 4)

__global__ void __launch_bounds__(256, 2)
mlp_mma_kernel(const float* __restrict__ nf,
               const float* __restrict__ b1, const float* __restrict__ b2,
               const float* __restrict__ b3, const float* __restrict__ gamma_p,
               const float* __restrict__ beta_p, float* __restrict__ out) {
    extern __shared__ float smem[];
    float* hs = smem;
    float* ws = hs + 128 * HS_STRIDE;
    float* xs = ws + 128 * WS_STRIDE;
    float* sBias = xs + 128 * XS_STRIDE;
    float* lnred = sBias + 5 * 128;

    const int tid = threadIdx.x;
    const int wid = tid >> 5;
    const int lid = tid & 31;
    const int grp = lid >> 2;
    const int tig = lid & 3;
    const int wr = wid & 3;
    const int wc = wid >> 2;
    const int rowA = wr * 32 + grp;
    const int base = blockIdx.x * TM;

    if (tid < 128) {
        sBias[tid]       = b1[tid];
        sBias[128 + tid] = b2[tid];
        sBias[256 + tid] = b3[tid];
        sBias[384 + tid] = gamma_p[tid];
        sBias[512 + tid] = beta_p[tid];
    }

    const int a_row = (lid & 7) + ((lid >> 3) & 1) * 8;
    const int a_col = (lid >> 4) * 4;
    const int b_row = (lid & 7) + (lid >> 4) * 8;
    const int b_col = ((lid >> 3) & 1) * 4;

    const uint32_t aX = smem_u32(xs) + (uint32_t)(((wr * 32 + a_row) * XS_STRIDE + a_col) * 4);
    const uint32_t aH = smem_u32(hs) + (uint32_t)(((wr * 32 + a_row) * HS_STRIDE + a_col) * 4);
    const uint32_t bWA = smem_u32(ws) + (uint32_t)(((wc * 64 + b_row) * WS_STRIDE + b_col) * 4);
    const uint32_t bWB = smem_u32(xs) + (uint32_t)(((wc * 64 + b_row) * XS_STRIDE + b_col) * 4);

    const int s_n = tid >> 3;
    const int s_q = tid & 7;
    const uint32_t stA = smem_u32(ws) + (uint32_t)((s_n * WS_STRIDE + s_q * 4) * 4);
    const uint32_t stB = smem_u32(xs) + (uint32_t)((s_n * XS_STRIDE + s_q * 4) * 4);

    float acc[16][4];
#pragma unroll
    for (int nt = 0; nt < 16; ++nt)
#pragma unroll
        for (int j = 0; j < 4; ++j) acc[nt][j] = 0.f;

#define MMA_STEP(abase, astrideB, bbase, aOff, bOff)                              \
    do {                                                                          \
        uint32_t a0[4], a1[4];                                                    \
        ldsm4(a0, (abase) + (aOff));                                              \
        ldsm4(a1, (abase) + (uint32_t)(16 * (astrideB)) + (aOff));                \
        _Pragma("unroll")                                                         \
        for (int nt2 = 0; nt2 < 4; ++nt2) {                                       \
            uint32_t b[4];                                                        \
            ldsm4(b, (bbase) + (uint32_t)(nt2 * 16 * WS_STRIDE * 4) + (bOff));    \
            MMA_TF32(acc[nt2 * 2],         a0[0], a0[1], a0[2], a0[3], b[0], b[1]); \
            MMA_TF32(acc[nt2 * 2 + 1],     a0[0], a0[1], a0[2], a0[3], b[2], b[3]); \
            MMA_TF32(acc[8 + nt2 * 2],     a1[0], a1[1], a1[2], a1[3], b[0], b[1]); \
            MMA_TF32(acc[8 + nt2 * 2 + 1], a1[0], a1[1], a1[2], a1[3], b[2], b[3]); \
        }                                                                         \
    } while (0)

    // ---------------- Layer 1 ----------------
    for (int kt = 0; kt < 8; ++kt) {
#pragma unroll
        for (int it = 0; it < 4; ++it) {
            int i = tid + it * 256;
            int row = i >> 3, q = i & 7;
            int gk = kt * 32 + q * 4;
            float4 v = make_float4(0.f, 0.f, 0.f, 0.f);
            int node = base + row;
            if (node < N_NODE) {
                const float* src = (gk < FD)
                    ? nf + (size_t)node * FD + gk
                    : g_agg + (size_t)node * FD + (gk - FD);
                v = *(const float4*)src;
            }
            v.x = to_tf32(v.x); v.y = to_tf32(v.y);
            v.z = to_tf32(v.z); v.w = to_tf32(v.w);
            *(float4*)(xs + row * XS_STRIDE + q * 4) = v;
            float4 w = *(const float4*)(g_Wt1 + (size_t)row * 256 + gk);
            *(float4*)(ws + row * WS_STRIDE + q * 4) = w;
        }
        __syncthreads();
#pragma unroll
        for (int ks = 0; ks < 4; ++ks)
            MMA_STEP(aX, XS_STRIDE * 4, bWA, (uint32_t)(ks * 32), (uint32_t)(ks * 32));
        __syncthreads();
    }

    // epilogue 1
#pragma unroll
    for (int mi = 0; mi < 2; ++mi) {
        int rA = rowA + mi * 16;
#pragma unroll
        for (int nt = 0; nt < 8; ++nt) {
            int col = wc * 64 + nt * 8 + tig * 2;
            float* a = acc[mi * 8 + nt];
            float2 v0, v1;
            v0.x = to_tf32(fmaxf(a[0] + sBias[col], 0.f));
            v0.y = to_tf32(fmaxf(a[1] + sBias[col + 1], 0.f));
            v1.x = to_tf32(fmaxf(a[2] + sBias[col], 0.f));
            v1.y = to_tf32(fmaxf(a[3] + sBias[col + 1], 0.f));
            *(float2*)(hs + rA * HS_STRIDE + col) = v0;
            *(float2*)(hs + (rA + 8) * HS_STRIDE + col) = v1;
        }
    }
    __syncthreads();

    // ---------------- Layers 2 & 3 (cp.async ping-pong) ----------------
#define ISSUE_W(Wt, kt, sbase)                                                    \
    _Pragma("unroll")                                                             \
    for (int it = 0; it < 4; ++it) {                                              \
        CP_ASYNC16((sbase) + (uint32_t)(it * 32 * WS_STRIDE * 4),                 \
                   (Wt) + (size_t)(s_n + it * 32) * 128 + (kt) * 32 + s_q * 4);   \
    }                                                                             \
    CP_COMMIT();

    for (int l = 0; l < 2; ++l) {
        const float* Wt = l ? g_Wt3 : g_Wt2;
#pragma unroll
        for (int nt = 0; nt < 16; ++nt)
#pragma unroll
            for (int j = 0; j < 4; ++j) acc[nt][j] = 0.f;

        ISSUE_W(Wt, 0, stA);
        for (int kt = 0; kt < 4; ++kt) {
            int bf = kt & 1;
            if (kt < 3) { ISSUE_W(Wt, kt + 1, bf == 0 ? stB : stA); CP_WAIT(1); }
            else CP_WAIT(0);
            __syncthreads();
            uint32_t bW = (bf == 0) ? bWA : bWB;
#pragma unroll
            for (int ks = 0; ks < 4; ++ks)
                MMA_STEP(aH, HS_STRIDE * 4, bW,
                         (uint32_t)((kt * 32 + ks * 8) * 4), (uint32_t)(ks * 32));
            __syncthreads();
        }

        if (l == 0) {
#pragma unroll
            for (int mi = 0; mi < 2; ++mi) {
                int rA = rowA + mi * 16;
#pragma unroll
                for (int nt = 0; nt < 8; ++nt) {
                    int col = wc * 64 + nt * 8 + tig * 2;
                    float* a = acc[mi * 8 + nt];
                    float2 v0, v1;
                    v0.x = to_tf32(fmaxf(a[0] + sBias[128 + col], 0.f));
                    v0.y = to_tf32(fmaxf(a[1] + sBias[128 + col + 1], 0.f));
                    v1.x = to_tf32(fmaxf(a[2] + sBias[128 + col], 0.f));
                    v1.y = to_tf32(fmaxf(a[3] + sBias[128 + col + 1], 0.f));
                    *(float2*)(hs + rA * HS_STRIDE + col) = v0;
                    *(float2*)(hs + (rA + 8) * HS_STRIDE + col) = v1;
                }
            }
            __syncthreads();
        }
    }

    // ---------------- Final: +b3, LN (cross-half), residual ----------------
    {
        float s[4] = {0.f, 0.f, 0.f, 0.f}, sq[4] = {0.f, 0.f, 0.f, 0.f};
#pragma unroll
        for (int mi = 0; mi < 2; ++mi)
#pragma unroll
            for (int nt = 0; nt < 8; ++nt) {
                int col = wc * 64 + nt * 8 + tig * 2;
                float* a = acc[mi * 8 + nt];
                a[0] += sBias[256 + col];
                a[1] += sBias[256 + col + 1];
                a[2] += sBias[256 + col];
                a[3] += sBias[256 + col + 1];
                s[mi * 2]      += a[0] + a[1];
                sq[mi * 2]     += a[0] * a[0] + a[1] * a[1];
                s[mi * 2 + 1]  += a[2] + a[3];
                sq[mi * 2 + 1] += a[2] * a[2] + a[3] * a[3];
            }
#pragma unroll
        for (int o = 1; o <= 2; o <<= 1)
#pragma unroll
            for (int p = 0; p < 4; ++p) {
                s[p] += __shfl_xor_sync(0xFFFFFFFFu, s[p], o);
                sq[p] += __shfl_xor_sync(0xFFFFFFFFu, sq[p], o);
            }
        if (tig == 0) {
#pragma unroll
            for (int p = 0; p < 4; ++p) {
                int row = rowA + (p >> 1) * 16 + (p & 1) * 8;
                lnred[row * 2 + wc] = s[p];
                lnred[256 + row * 2 + wc] = sq[p];
            }
        }
        __syncthreads();
        float mu[4], ri[4];
#pragma unroll
        for (int p = 0; p < 4; ++p) {
            int row = rowA + (p >> 1) * 16 + (p & 1) * 8;
            float st = lnred[row * 2] + lnred[row * 2 + 1];
            float qt = lnred[256 + row * 2] + lnred[256 + row * 2 + 1];
            mu[p] = st * (1.f / 128.f);
            ri[p] = rsqrtf(qt * (1.f / 128.f) - mu[p] * mu[p] + EPS);
        }
#pragma unroll
        for (int mi = 0; mi < 2; ++mi)
#pragma unroll
            for (int nt = 0; nt < 8; ++nt) {
                int col = wc * 64 + nt * 8 + tig * 2;
                float g0 = sBias[384 + col], g1 = sBias[384 + col + 1];
                float be0 = sBias[512 + col], be1 = sBias[512 + col + 1];
                float* a = acc[mi * 8 + nt];
                int rTop = base + rowA + mi * 16;
                int rBot = rTop + 8;
                int pT = mi * 2, pB = mi * 2 + 1;
                if (rTop < N_NODE) {
                    float2 nv = *(const float2*)(nf + (size_t)rTop * FD + col);
                    float2 o;
                    o.x = (a[0] - mu[pT]) * ri[pT] * g0 + be0 + nv.x;
                    o.y = (a[1] - mu[pT]) * ri[pT] * g1 + be1 + nv.y;
                    *(float2*)(out + (size_t)rTop * FD + col) = o;
                }
                if (rBot < N_NODE) {
                    float2 nv = *(const float2*)(nf + (size_t)rBot * FD + col);
                    float2 o;
                    o.x = (a[2] - mu[pB]) * ri[pB] * g0 + be0 + nv.x;
                    o.y = (a[3] - mu[pB]) * ri[pB] * g1 + be1 + nv.y;
                    *(float2*)(out + (size_t)rBot * FD + col) = o;
                }
            }
    }
}

// ---------------------------------------------------------------------------
extern "C" void kernel_launch(void* const* d_in, const int* in_sizes, int n_in,
                              void* d_out, int out_size) {
    const float* node_feature = (const float*)d_in[0];
    const int* edge_matrix    = (const int*)d_in[1];
    const float* edge_feature = (const float*)d_in[2];
    const float* W1 = (const float*)d_in[3];
    const float* b1 = (const float*)d_in[4];
    const float* W2 = (const float*)d_in[5];
    const float* b2 = (const float*)d_in[6];
    const float* W3 = (const float*)d_in[7];
    const float* b3 = (const float*)d_in[8];
    const float* gamma = (const float*)d_in[9];
    const float* beta  = (const float*)d_in[10];
    float* out = (float*)d_out;

    static void* agg_ptr = nullptr;
    static int inited = 0;
    if (!inited) {
        cudaGetSymbolAddress(&agg_ptr, g_agg);
        cudaFuncSetAttribute(mlp_mma_kernel,
                             cudaFuncAttributeMaxDynamicSharedMemorySize, SMEM_BYTES);
        inited = 1;
    }

    cudaMemsetAsync(agg_ptr, 0, (size_t)N_NODE * FD * sizeof(float));

    int nwarp = (N_EDGE + 3) / 4;
    scatter_edges_kernel<<<(nwarp + 7) / 8, 256>>>(edge_matrix, edge_feature);

    prep_weights_kernel<<<(256 * 128 + 2 * 128 * 128 + 255) / 256, 256>>>(W1, W2, W3);

    int grid = (N_NODE + TM - 1) / TM;
    mlp_mma_kernel<<<grid, 256, SMEM_BYTES>>>(node_feature, b1, b2, b3,
                                              gamma, beta, out);
}

// round 17
// speedup vs baseline: 1.1909x; 1.1909x over previous
#include <cuda_runtime.h>
#include <cstdint>
#include <cstddef>

#define N_NODE 50000
#define N_EDGE 625000
#define FD 128
#define EPS 1e-5f
#define TM 128

__device__ float g_agg[(size_t)N_NODE * FD];
__device__ float g_Wt1[128 * 256];
__device__ float g_Wt2[128 * 128];
__device__ float g_Wt3[128 * 128];

__device__ __forceinline__ float to_tf32(float x) {
    uint32_t r;
    asm("cvt.rna.tf32.f32 %0, %1;" : "=r"(r) : "f"(x));
    return __uint_as_float(r);
}
__device__ __forceinline__ uint32_t smem_u32(const void* p) {
    uint32_t a;
    asm("{ .reg .u64 t; cvta.to.shared.u64 t, %1; cvt.u32.u64 %0, t; }"
        : "=r"(a) : "l"(p));
    return a;
}
__device__ __forceinline__ void ldsm4(uint32_t a[4], uint32_t addr) {
    asm volatile("ldmatrix.sync.aligned.m8n8.x4.shared.b16 {%0,%1,%2,%3}, [%4];"
                 : "=r"(a[0]), "=r"(a[1]), "=r"(a[2]), "=r"(a[3]) : "r"(addr));
}

#define MMA_TF32(c, a0, a1, a2, a3, b0, b1)                                       \
    asm volatile("mma.sync.aligned.m16n8k8.row.col.f32.tf32.tf32.f32 "            \
                 "{%0,%1,%2,%3}, {%4,%5,%6,%7}, {%8,%9}, {%0,%1,%2,%3};"          \
                 : "+f"((c)[0]), "+f"((c)[1]), "+f"((c)[2]), "+f"((c)[3])         \
                 : "r"(a0), "r"(a1), "r"(a2), "r"(a3), "r"(b0), "r"(b1))

#define CP_ASYNC16(saddr, gptr)                                                   \
    asm volatile("cp.async.cg.shared.global [%0], [%1], 16;"                      \
                 :: "r"(saddr), "l"(gptr) : "memory")
#define CP_COMMIT() asm volatile("cp.async.commit_group;" ::: "memory")
#define CP_WAIT(n)  asm volatile("cp.async.wait_group %0;" :: "n"(n) : "memory")

// ---------------------------------------------------------------------------
// Scatter-add: 4 edges/warp, MLP=4 (measured optimum)
// ---------------------------------------------------------------------------
__global__ void scatter_edges_kernel(const int* __restrict__ em,
                                     const float* __restrict__ ef) {
    int e0 = (blockIdx.x * 8 + (threadIdx.x >> 5)) * 4;
    int lane = threadIdx.x & 31;
    if (e0 + 3 < N_EDGE) {
        int r0 = em[N_EDGE + e0];
        int r1 = em[N_EDGE + e0 + 1];
        int r2 = em[N_EDGE + e0 + 2];
        int r3 = em[N_EDGE + e0 + 3];
        float4 v0 = *(const float4*)(ef + (size_t)(e0    ) * FD + lane * 4);
        float4 v1 = *(const float4*)(ef + (size_t)(e0 + 1) * FD + lane * 4);
        float4 v2 = *(const float4*)(ef + (size_t)(e0 + 2) * FD + lane * 4);
        float4 v3 = *(const float4*)(ef + (size_t)(e0 + 3) * FD + lane * 4);
        asm volatile("red.global.add.v4.f32 [%0], {%1,%2,%3,%4};"
                     :: "l"(g_agg + (size_t)r0 * FD + lane * 4),
                        "f"(v0.x), "f"(v0.y), "f"(v0.z), "f"(v0.w) : "memory");
        asm volatile("red.global.add.v4.f32 [%0], {%1,%2,%3,%4};"
                     :: "l"(g_agg + (size_t)r1 * FD + lane * 4),
                        "f"(v1.x), "f"(v1.y), "f"(v1.z), "f"(v1.w) : "memory");
        asm volatile("red.global.add.v4.f32 [%0], {%1,%2,%3,%4};"
                     :: "l"(g_agg + (size_t)r2 * FD + lane * 4),
                        "f"(v2.x), "f"(v2.y), "f"(v2.z), "f"(v2.w) : "memory");
        asm volatile("red.global.add.v4.f32 [%0], {%1,%2,%3,%4};"
                     :: "l"(g_agg + (size_t)r3 * FD + lane * 4),
                        "f"(v3.x), "f"(v3.y), "f"(v3.z), "f"(v3.w) : "memory");
    } else {
        for (int i = 0; i < 4; ++i) {
            int e = e0 + i;
            if (e >= N_EDGE) break;
            int r = em[N_EDGE + e];
            float4 v = *(const float4*)(ef + (size_t)e * FD + lane * 4);
            asm volatile("red.global.add.v4.f32 [%0], {%1,%2,%3,%4};"
                         :: "l"(g_agg + (size_t)r * FD + lane * 4),
                            "f"(v.x), "f"(v.y), "f"(v.z), "f"(v.w) : "memory");
        }
    }
}

// ---------------------------------------------------------------------------
__global__ void prep_weights_kernel(const float* __restrict__ W1,
                                    const float* __restrict__ W2,
                                    const float* __restrict__ W3) {
    int i = blockIdx.x * blockDim.x + threadIdx.x;
    if (i < 256 * 128) {
        int k = i >> 7, n = i & 127;
        g_Wt1[n * 256 + k] = to_tf32(W1[i]);
    } else if (i < 256 * 128 + 128 * 128) {
        int j = i - 256 * 128;
        int k = j >> 7, n = j & 127;
        g_Wt2[n * 128 + k] = to_tf32(W2[j]);
    } else if (i < 256 * 128 + 2 * 128 * 128) {
        int j = i - 256 * 128 - 128 * 128;
        int k = j >> 7, n = j & 127;
        g_Wt3[n * 128 + k] = to_tf32(W3[j]);
    }
}

// ---------------------------------------------------------------------------
// Fused MLP + LN + residual. Warp tile 32x64 (2x B-fragment reuse).
// ---------------------------------------------------------------------------
#define XS_STRIDE 36
#define WS_STRIDE 36
#define HS_STRIDE 132
#define SMEM_FLOATS (128 * HS_STRIDE + 128 * WS_STRIDE + 128 * XS_STRIDE + 5 * 128 + 512)
#define SMEM_BYTES (SMEM_FLOATS * 4)

__global__ void __launch_bounds__(256, 2)
mlp_mma_kernel(const float* __restrict__ nf,
               const float* __restrict__ b1, const float* __restrict__ b2,
               const float* __restrict__ b3, const float* __restrict__ gamma_p,
               const float* __restrict__ beta_p, float* __restrict__ out) {
    extern __shared__ float smem[];
    float* hs = smem;
    float* ws = hs + 128 * HS_STRIDE;
    float* xs = ws + 128 * WS_STRIDE;
    float* sBias = xs + 128 * XS_STRIDE;
    float* lnred = sBias + 5 * 128;

    const int tid = threadIdx.x;
    const int wid = tid >> 5;
    const int lid = tid & 31;
    const int grp = lid >> 2;
    const int tig = lid & 3;
    const int wr = wid & 3;
    const int wc = wid >> 2;
    const int rowA = wr * 32 + grp;
    const int base = blockIdx.x * TM;

    if (tid < 128) {
        sBias[tid]       = b1[tid];
        sBias[128 + tid] = b2[tid];
        sBias[256 + tid] = b3[tid];
        sBias[384 + tid] = gamma_p[tid];
        sBias[512 + tid] = beta_p[tid];
    }

    const int a_row = (lid & 7) + ((lid >> 3) & 1) * 8;
    const int a_col = (lid >> 4) * 4;
    const int b_row = (lid & 7) + (lid >> 4) * 8;
    const int b_col = ((lid >> 3) & 1) * 4;

    const uint32_t aX = smem_u32(xs) + (uint32_t)(((wr * 32 + a_row) * XS_STRIDE + a_col) * 4);
    const uint32_t aH = smem_u32(hs) + (uint32_t)(((wr * 32 + a_row) * HS_STRIDE + a_col) * 4);
    const uint32_t bWA = smem_u32(ws) + (uint32_t)(((wc * 64 + b_row) * WS_STRIDE + b_col) * 4);
    const uint32_t bWB = smem_u32(xs) + (uint32_t)(((wc * 64 + b_row) * XS_STRIDE + b_col) * 4);

    const int s_n = tid >> 3;
    const int s_q = tid & 7;
    const uint32_t stA = smem_u32(ws) + (uint32_t)((s_n * WS_STRIDE + s_q * 4) * 4);
    const uint32_t stB = smem_u32(xs) + (uint32_t)((s_n * XS_STRIDE + s_q * 4) * 4);

    float acc[16][4];
#pragma unroll
    for (int nt = 0; nt < 16; ++nt)
#pragma unroll
        for (int j = 0; j < 4; ++j) acc[nt][j] = 0.f;

#define MMA_STEP(abase, astrideB, bbase, aOff, bOff)                              \
    do {                                                                          \
        uint32_t a0[4], a1[4];                                                    \
        ldsm4(a0, (abase) + (aOff));                                              \
        ldsm4(a1, (abase) + (uint32_t)(16 * (astrideB)) + (aOff));                \
        _Pragma("unroll")                                                         \
        for (int nt2 = 0; nt2 < 4; ++nt2) {                                       \
            uint32_t b[4];                                                        \
            ldsm4(b, (bbase) + (uint32_t)(nt2 * 16 * WS_STRIDE * 4) + (bOff));    \
            MMA_TF32(acc[nt2 * 2],         a0[0], a0[1], a0[2], a0[3], b[0], b[1]); \
            MMA_TF32(acc[nt2 * 2 + 1],     a0[0], a0[1], a0[2], a0[3], b[2], b[3]); \
            MMA_TF32(acc[8 + nt2 * 2],     a1[0], a1[1], a1[2], a1[3], b[0], b[1]); \
            MMA_TF32(acc[8 + nt2 * 2 + 1], a1[0], a1[1], a1[2], a1[3], b[2], b[3]); \
        }                                                                         \
    } while (0)

    // ---------------- Layer 1 ----------------
    for (int kt = 0; kt < 8; ++kt) {
#pragma unroll
        for (int it = 0; it < 4; ++it) {
            int i = tid + it * 256;
            int row = i >> 3, q = i & 7;
            int gk = kt * 32 + q * 4;
            float4 v = make_float4(0.f, 0.f, 0.f, 0.f);
            int node = base + row;
            if (node < N_NODE) {
                const float* src = (gk < FD)
                    ? nf + (size_t)node * FD + gk
                    : g_agg + (size_t)node * FD + (gk - FD);
                v = *(const float4*)src;
            }
            v.x = to_tf32(v.x); v.y = to_tf32(v.y);
            v.z = to_tf32(v.z); v.w = to_tf32(v.w);
            *(float4*)(xs + row * XS_STRIDE + q * 4) = v;
            float4 w = *(const float4*)(g_Wt1 + (size_t)row * 256 + gk);
            *(float4*)(ws + row * WS_STRIDE + q * 4) = w;
        }
        __syncthreads();
#pragma unroll
        for (int ks = 0; ks < 4; ++ks)
            MMA_STEP(aX, XS_STRIDE * 4, bWA, (uint32_t)(ks * 32), (uint32_t)(ks * 32));
        __syncthreads();
    }

    // epilogue 1
#pragma unroll
    for (int mi = 0; mi < 2; ++mi) {
        int rA = rowA + mi * 16;
#pragma unroll
        for (int nt = 0; nt < 8; ++nt) {
            int col = wc * 64 + nt * 8 + tig * 2;
            float* a = acc[mi * 8 + nt];
            float2 v0, v1;
            v0.x = to_tf32(fmaxf(a[0] + sBias[col], 0.f));
            v0.y = to_tf32(fmaxf(a[1] + sBias[col + 1], 0.f));
            v1.x = to_tf32(fmaxf(a[2] + sBias[col], 0.f));
            v1.y = to_tf32(fmaxf(a[3] + sBias[col + 1], 0.f));
            *(float2*)(hs + rA * HS_STRIDE + col) = v0;
            *(float2*)(hs + (rA + 8) * HS_STRIDE + col) = v1;
        }
    }
    __syncthreads();

    // ---------------- Layers 2 & 3 (cp.async ping-pong) ----------------
#define ISSUE_W(Wt, kt, sbase)                                                    \
    _Pragma("unroll")                                                             \
    for (int it = 0; it < 4; ++it) {                                              \
        CP_ASYNC16((sbase) + (uint32_t)(it * 32 * WS_STRIDE * 4),                 \
                   (Wt) + (size_t)(s_n + it * 32) * 128 + (kt) * 32 + s_q * 4);   \
    }                                                                             \
    CP_COMMIT();

    for (int l = 0; l < 2; ++l) {
        const float* Wt = l ? g_Wt3 : g_Wt2;
#pragma unroll
        for (int nt = 0; nt < 16; ++nt)
#pragma unroll
            for (int j = 0; j < 4; ++j) acc[nt][j] = 0.f;

        ISSUE_W(Wt, 0, stA);
        for (int kt = 0; kt < 4; ++kt) {
            int bf = kt & 1;
            if (kt < 3) { ISSUE_W(Wt, kt + 1, bf == 0 ? stB : stA); CP_WAIT(1); }
            else CP_WAIT(0);
            __syncthreads();
            uint32_t bW = (bf == 0) ? bWA : bWB;
#pragma unroll
            for (int ks = 0; ks < 4; ++ks)
                MMA_STEP(aH, HS_STRIDE * 4, bW,
                         (uint32_t)((kt * 32 + ks * 8) * 4), (uint32_t)(ks * 32));
            __syncthreads();
        }

        if (l == 0) {
#pragma unroll
            for (int mi = 0; mi < 2; ++mi) {
                int rA = rowA + mi * 16;
#pragma unroll
                for (int nt = 0; nt < 8; ++nt) {
                    int col = wc * 64 + nt * 8 + tig * 2;
                    float* a = acc[mi * 8 + nt];
                    float2 v0, v1;
                    v0.x = to_tf32(fmaxf(a[0] + sBias[128 + col], 0.f));
                    v0.y = to_tf32(fmaxf(a[1] + sBias[128 + col + 1], 0.f));
                    v1.x = to_tf32(fmaxf(a[2] + sBias[128 + col], 0.f));
                    v1.y = to_tf32(fmaxf(a[3] + sBias[128 + col + 1], 0.f));
                    *(float2*)(hs + rA * HS_STRIDE + col) = v0;
                    *(float2*)(hs + (rA + 8) * HS_STRIDE + col) = v1;
                }
            }
            __syncthreads();
        }
    }

    // ---------------- Final: +b3, LN (cross-half), residual ----------------
    {
        float s[4] = {0.f, 0.f, 0.f, 0.f}, sq[4] = {0.f, 0.f, 0.f, 0.f};
#pragma unroll
        for (int mi = 0; mi < 2; ++mi)
#pragma unroll
            for (int nt = 0; nt < 8; ++nt) {
                int col = wc * 64 + nt * 8 + tig * 2;
                float* a = acc[mi * 8 + nt];
                a[0] += sBias[256 + col];
                a[1] += sBias[256 + col + 1];
                a[2] += sBias[256 + col];
                a[3] += sBias[256 + col + 1];
                s[mi * 2]      += a[0] + a[1];
                sq[mi * 2]     += a[0] * a[0] + a[1] * a[1];
                s[mi * 2 + 1]  += a[2] + a[3];
                sq[mi * 2 + 1] += a[2] * a[2] + a[3] * a[3];
            }
#pragma unroll
        for (int o = 1; o <= 2; o <<= 1)
#pragma unroll
            for (int p = 0; p < 4; ++p) {
                s[p] += __shfl_xor_sync(0xFFFFFFFFu, s[p], o);
                sq[p] += __shfl_xor_sync(0xFFFFFFFFu, sq[p], o);
            }
        if (tig == 0) {
#pragma unroll
            for (int p = 0; p < 4; ++p) {
                int row = rowA + (p >> 1) * 16 + (p & 1) * 8;
                lnred[row * 2 + wc] = s[p];
                lnred[256 + row * 2 + wc] = sq[p];
            }
        }
        __syncthreads();
        float mu[4], ri[4];
#pragma unroll
        for (int p = 0; p < 4; ++p) {
            int row = rowA + (p >> 1) * 16 + (p & 1) * 8;
            float st = lnred[row * 2] + lnred[row * 2 + 1];
            float qt = lnred[256 + row * 2] + lnred[256 + row * 2 + 1];
            mu[p] = st * (1.f / 128.f);
            ri[p] = rsqrtf(qt * (1.f / 128.f) - mu[p] * mu[p] + EPS);
        }
#pragma unroll
        for (int mi = 0; mi < 2; ++mi)
#pragma unroll
            for (int nt = 0; nt < 8; ++nt) {
                int col = wc * 64 + nt * 8 + tig * 2;
                float g0 = sBias[384 + col], g1 = sBias[384 + col + 1];
                float be0 = sBias[512 + col], be1 = sBias[512 + col + 1];
                float* a = acc[mi * 8 + nt];
                int rTop = base + rowA + mi * 16;
                int rBot = rTop + 8;
                int pT = mi * 2, pB = mi * 2 + 1;
                if (rTop < N_NODE) {
                    float2 nv = *(const float2*)(nf + (size_t)rTop * FD + col);
                    float2 o;
                    o.x = (a[0] - mu[pT]) * ri[pT] * g0 + be0 + nv.x;
                    o.y = (a[1] - mu[pT]) * ri[pT] * g1 + be1 + nv.y;
                    *(float2*)(out + (size_t)rTop * FD + col) = o;
                }
                if (rBot < N_NODE) {
                    float2 nv = *(const float2*)(nf + (size_t)rBot * FD + col);
                    float2 o;
                    o.x = (a[2] - mu[pB]) * ri[pB] * g0 + be0 + nv.x;
                    o.y = (a[3] - mu[pB]) * ri[pB] * g1 + be1 + nv.y;
                    *(float2*)(out + (size_t)rBot * FD + col) = o;
                }
            }
    }
}

// ---------------------------------------------------------------------------
extern "C" void kernel_launch(void* const* d_in, const int* in_sizes, int n_in,
                              void* d_out, int out_size) {
    const float* node_feature = (const float*)d_in[0];
    const int* edge_matrix    = (const int*)d_in[1];
    const float* edge_feature = (const float*)d_in[2];
    const float* W1 = (const float*)d_in[3];
    const float* b1 = (const float*)d_in[4];
    const float* W2 = (const float*)d_in[5];
    const float* b2 = (const float*)d_in[6];
    const float* W3 = (const float*)d_in[7];
    const float* b3 = (const float*)d_in[8];
    const float* gamma = (const float*)d_in[9];
    const float* beta  = (const float*)d_in[10];
    float* out = (float*)d_out;

    static void* agg_ptr = nullptr;
    static int inited = 0;
    if (!inited) {
        cudaGetSymbolAddress(&agg_ptr, g_agg);
        cudaFuncSetAttribute(mlp_mma_kernel,
                             cudaFuncAttributeMaxDynamicSharedMemorySize, SMEM_BYTES);
        inited = 1;
    }

    cudaMemsetAsync(agg_ptr, 0, (size_t)N_NODE * FD * sizeof(float));

    int nwarp = (N_EDGE + 3) / 4;
    scatter_edges_kernel<<<(nwarp + 7) / 8, 256>>>(edge_matrix, edge_feature);

    prep_weights_kernel<<<(256 * 128 + 2 * 128 * 128 + 255) / 256, 256>>>(W1, W2, W3);

    int grid = (N_NODE + TM - 1) / TM;
    mlp_mma_kernel<<<grid, 256, SMEM_BYTES>>>(node_feature, b1, b2, b3,
                                              gamma, beta, out);
}